// round 3
// baseline (speedup 1.0000x reference)
#include <cuda_runtime.h>
#include <math.h>

// ---------------- problem constants ----------------
#define BB   4
#define LL   2048
#define DMD  1024
#define EDD  2048
#define SEGD 256
#define NSEG 8
#define DTRD 64
#define NSTD 2
#define NCD  66            // DTR + N
#define MROWS (BB*LL)      // 8192
#define MSEG  (BB*SEGD)    // 1024

// ---------------- scratch (device globals; no mallocs allowed) ----------------
__device__ float g_xn   [MROWS*DMD];
__device__ float g_xz   [MROWS*2*EDD];
__device__ float g_xs   [MROWS*EDD];
__device__ float g_dC   [MROWS*NCD];
__device__ float g_dr   [MROWS*DTRD];
__device__ float g_Cm   [MROWS*NSTD];
__device__ float g_delta[MROWS*EDD];
__device__ float g_y    [MROWS*EDD];
__device__ float g_gate [MROWS*EDD];
__device__ float g_K    [MSEG*EDD];
__device__ float g_Kerr [MSEG*EDD];
__device__ float g_Kdy  [MSEG*EDD];
__device__ float g_Knew [MSEG*EDD];
__device__ float g_h1   [MSEG*3*EDD];
__device__ float g_h2   [MSEG*EDD];

// ---------------- generic GEMM: C[M,N] = A[M,K] @ B[N,K]^T ----------------
// EPI: 0 none, 1 bias+relu, 2 relu, 3 bias+softplus, 4 accumulate (C += acc)
// Requires: M % 128 == 0, K % 16 == 0. N arbitrary (guarded).
// Double-buffered shared tiles: global prefetch overlaps the FFMA block.
template<int EPI>
__global__ __launch_bounds__(256) void gemm_tn(
    const float* __restrict__ A, const float* __restrict__ Bw,
    const float* __restrict__ bias, float* __restrict__ C,
    int M, int N, int K)
{
    __shared__ float As[2][16][128];
    __shared__ float Bs[2][16][128];
    const int tid = threadIdx.x;
    const int m0 = blockIdx.y * 128;
    const int n0 = blockIdx.x * 128;
    const int tx = tid & 15;       // n direction
    const int ty = tid >> 4;       // m direction

    float acc[8][8];
#pragma unroll
    for (int i = 0; i < 8; i++)
#pragma unroll
        for (int j = 0; j < 8; j++) acc[i][j] = 0.f;

    const int lrow = tid >> 1;          // 0..127
    const int lcol = (tid & 1) * 8;     // 0 or 8
    const float* Aptr = A + (size_t)(m0 + lrow) * K + lcol;
    const bool bvalid = (n0 + lrow) < N;
    const float* Bptr = Bw + (size_t)(n0 + lrow) * K + lcol;

    // prologue: load first K-tile into buffer 0
    {
        float4 a0 = *(const float4*)(Aptr);
        float4 a1 = *(const float4*)(Aptr + 4);
        float4 b0 = make_float4(0.f, 0.f, 0.f, 0.f);
        float4 b1 = make_float4(0.f, 0.f, 0.f, 0.f);
        if (bvalid) {
            b0 = *(const float4*)(Bptr);
            b1 = *(const float4*)(Bptr + 4);
        }
        As[0][lcol + 0][lrow] = a0.x; As[0][lcol + 1][lrow] = a0.y;
        As[0][lcol + 2][lrow] = a0.z; As[0][lcol + 3][lrow] = a0.w;
        As[0][lcol + 4][lrow] = a1.x; As[0][lcol + 5][lrow] = a1.y;
        As[0][lcol + 6][lrow] = a1.z; As[0][lcol + 7][lrow] = a1.w;
        Bs[0][lcol + 0][lrow] = b0.x; Bs[0][lcol + 1][lrow] = b0.y;
        Bs[0][lcol + 2][lrow] = b0.z; Bs[0][lcol + 3][lrow] = b0.w;
        Bs[0][lcol + 4][lrow] = b1.x; Bs[0][lcol + 5][lrow] = b1.y;
        Bs[0][lcol + 6][lrow] = b1.z; Bs[0][lcol + 7][lrow] = b1.w;
    }
    __syncthreads();

    int nbuf = 1;   // next buffer to write
    for (int k0 = 0; k0 < K; k0 += 16) {
        const int cur = nbuf ^ 1;
        const bool more = (k0 + 16) < K;

        // prefetch next K-tile into registers (latency hides behind FFMAs)
        float4 a0, a1, b0, b1;
        if (more) {
            a0 = *(const float4*)(Aptr + k0 + 16);
            a1 = *(const float4*)(Aptr + k0 + 20);
            b0 = make_float4(0.f, 0.f, 0.f, 0.f);
            b1 = make_float4(0.f, 0.f, 0.f, 0.f);
            if (bvalid) {
                b0 = *(const float4*)(Bptr + k0 + 16);
                b1 = *(const float4*)(Bptr + k0 + 20);
            }
        }

        // compute on current buffer
#pragma unroll
        for (int kk = 0; kk < 16; kk++) {
            float ra[8], rb[8];
            *(float4*)(ra)     = *(const float4*)(&As[cur][kk][ty * 8]);
            *(float4*)(ra + 4) = *(const float4*)(&As[cur][kk][ty * 8 + 4]);
            *(float4*)(rb)     = *(const float4*)(&Bs[cur][kk][tx * 8]);
            *(float4*)(rb + 4) = *(const float4*)(&Bs[cur][kk][tx * 8 + 4]);
#pragma unroll
            for (int i = 0; i < 8; i++)
#pragma unroll
                for (int j = 0; j < 8; j++)
                    acc[i][j] = fmaf(ra[i], rb[j], acc[i][j]);
        }
        __syncthreads();   // everyone done reading buffer `cur`

        if (more) {
            As[nbuf][lcol + 0][lrow] = a0.x; As[nbuf][lcol + 1][lrow] = a0.y;
            As[nbuf][lcol + 2][lrow] = a0.z; As[nbuf][lcol + 3][lrow] = a0.w;
            As[nbuf][lcol + 4][lrow] = a1.x; As[nbuf][lcol + 5][lrow] = a1.y;
            As[nbuf][lcol + 6][lrow] = a1.z; As[nbuf][lcol + 7][lrow] = a1.w;
            Bs[nbuf][lcol + 0][lrow] = b0.x; Bs[nbuf][lcol + 1][lrow] = b0.y;
            Bs[nbuf][lcol + 2][lrow] = b0.z; Bs[nbuf][lcol + 3][lrow] = b0.w;
            Bs[nbuf][lcol + 4][lrow] = b1.x; Bs[nbuf][lcol + 5][lrow] = b1.y;
            Bs[nbuf][lcol + 6][lrow] = b1.z; Bs[nbuf][lcol + 7][lrow] = b1.w;
            __syncthreads();
            nbuf ^= 1;
        }
    }

    const int mbase = m0 + ty * 8;
    const int nbase = n0 + tx * 8;
#pragma unroll
    for (int i = 0; i < 8; i++) {
#pragma unroll
        for (int j = 0; j < 8; j++) {
            int n = nbase + j;
            if (n >= N) continue;
            size_t idx = (size_t)(mbase + i) * N + n;
            float v = acc[i][j];
            if (EPI == 0) {
                C[idx] = v;
            } else if (EPI == 1) {
                C[idx] = fmaxf(v + bias[n], 0.f);
            } else if (EPI == 2) {
                C[idx] = fmaxf(v, 0.f);
            } else if (EPI == 3) {
                float u = v + bias[n];
                C[idx] = (u > 15.f) ? u : log1pf(expf(u));
            } else { // 4
                C[idx] += v;
            }
        }
    }
}

// ---------------- RMSNorm over last dim DM ----------------
__global__ void rmsnorm_kernel(const float* __restrict__ h,
                               const float* __restrict__ w,
                               float* __restrict__ out)
{
    __shared__ float red[256];
    int row = blockIdx.x;
    const float* hr = h + (size_t)row * DMD;
    float s = 0.f;
    for (int j = threadIdx.x; j < DMD; j += 256) { float v = hr[j]; s += v * v; }
    red[threadIdx.x] = s; __syncthreads();
    for (int o = 128; o > 0; o >>= 1) {
        if (threadIdx.x < o) red[threadIdx.x] += red[threadIdx.x + o];
        __syncthreads();
    }
    float scale = rsqrtf(red[0] * (1.f / DMD) + 1e-5f);
    for (int j = threadIdx.x; j < DMD; j += 256)
        out[(size_t)row * DMD + j] = hr[j] * scale * w[j];
}

// ---------------- fused 2x depthwise conv (DCONV=2, causal) + SiLU ----------------
__global__ void conv_silu_kernel(const float* __restrict__ xz,
                                 const float* __restrict__ c1w, const float* __restrict__ c1b,
                                 const float* __restrict__ c2w, const float* __restrict__ c2b,
                                 float* __restrict__ xs)
{
    size_t idx = (size_t)blockIdx.x * blockDim.x + threadIdx.x;
    if (idx >= (size_t)MROWS * EDD) return;
    int e  = (int)(idx & (EDD - 1));
    int bl = (int)(idx >> 11);        // b*L + l
    int l  = bl & (LL - 1);
    float x0  = xz[(size_t)bl * (2 * EDD) + e];
    float xm1 = (l >= 1) ? xz[(size_t)(bl - 1) * (2 * EDD) + e] : 0.f;
    float xm2 = (l >= 2) ? xz[(size_t)(bl - 2) * (2 * EDD) + e] : 0.f;
    float w10 = c1w[e * 2 + 0], w11 = c1w[e * 2 + 1], b1 = c1b[e];
    float w20 = c2w[e * 2 + 0], w21 = c2w[e * 2 + 1], b2 = c2b[e];
    float t1l   = b1 + w10 * xm1 + w11 * x0;
    float t1lm1 = (l >= 1) ? (b1 + w10 * xm2 + w11 * xm1) : 0.f;
    float u = b2 + w20 * t1lm1 + w21 * t1l;
    xs[idx] = u / (1.f + expf(-u));
}

// ---------------- split dC into dr (cols<64) and C (cols 64..65) ----------------
__global__ void split_dC_kernel(const float* __restrict__ dC,
                                float* __restrict__ dr, float* __restrict__ Cm)
{
    int idx = blockIdx.x * blockDim.x + threadIdx.x;
    if (idx >= MROWS * NCD) return;
    int m = idx / NCD, c = idx % NCD;
    float v = dC[idx];
    if (c < DTRD) dr[m * DTRD + c] = v;
    else          Cm[m * NSTD + (c - DTRD)] = v;
}

// ---------------- Kerr = softsign((xg - yh)^2) ----------------
__global__ void kerr_kernel(const float* __restrict__ xs,
                            const float* __restrict__ y,
                            float* __restrict__ kerr, int s0)
{
    size_t idx = (size_t)blockIdx.x * blockDim.x + threadIdx.x;
    if (idx >= (size_t)MSEG * EDD) return;
    int e  = (int)(idx & (EDD - 1));
    int bt = (int)(idx >> 11);
    int t = bt & (SEGD - 1);
    int b = bt >> 8;
    size_t src = ((size_t)(b * LL + s0 + t)) * EDD + e;
    float xg = xs[src];
    float yh = (s0 > 0) ? y[((size_t)(b * LL + s0 - SEGD + t)) * EDD + e] : 0.f;
    float d = xg - yh;
    float u = d * d;
    kerr[idx] = u / (1.f + u);
}

// ---------------- LayerNorm(Knew) + EMA update of K ----------------
__global__ void ln_kupdate_kernel(const float* __restrict__ Kn,
                                  const float* __restrict__ lng, const float* __restrict__ lnb,
                                  const float* __restrict__ ka, float* __restrict__ Kst)
{
    __shared__ float srow[EDD];
    __shared__ float red[256];
    int row = blockIdx.x;
    int tid = threadIdx.x;
    const float* hr = Kn + (size_t)row * EDD;
    float s = 0.f;
    for (int j = tid; j < EDD; j += 256) { float v = hr[j]; srow[j] = v; s += v; }
    red[tid] = s; __syncthreads();
    for (int o = 128; o > 0; o >>= 1) {
        if (tid < o) red[tid] += red[tid + o];
        __syncthreads();
    }
    float mu = red[0] * (1.f / EDD);
    __syncthreads();
    float s2 = 0.f;
    for (int j = tid; j < EDD; j += 256) { float d = srow[j] - mu; s2 += d * d; }
    red[tid] = s2; __syncthreads();
    for (int o = 128; o > 0; o >>= 1) {
        if (tid < o) red[tid] += red[tid + o];
        __syncthreads();
    }
    float rstd = rsqrtf(red[0] * (1.f / EDD) + 1e-5f);
    for (int j = tid; j < EDD; j += 256) {
        float o = lng[j] * (srow[j] - mu) * rstd + lnb[j];
        float a = fminf(fmaxf(ka[j], 0.01f), 0.99f);
        size_t id = (size_t)row * EDD + j;
        Kst[id] = (1.f - a) * Kst[id] + a * o;
    }
}

// ---------------- FDU: DFT -> omega*g filter -> IDFT(real) ; Kdy = K * fdu ----------------
__global__ void fdu_kernel(const float* __restrict__ xs,
                           const float* __restrict__ delta,
                           const float* __restrict__ Kst,
                           float* __restrict__ Kdy,
                           const float* __restrict__ sigma, int layer, int s0)
{
    __shared__ float sx[SEGD], twc[SEGD], tws[SEGD], Sre[SEGD], Sim[SEGD];
    int t = threadIdx.x;                 // time index & frequency index
    int be = blockIdx.x;                 // b*ED + e
    int b = be >> 11, e = be & (EDD - 1);
    float cc, ss;
    sincospif((float)t * (1.0f / 128.0f), &ss, &cc);   // angle 2*pi*t/256
    twc[t] = cc; tws[t] = ss;
    sx[t] = xs[((size_t)(b * LL + s0 + t)) * EDD + e];
    __syncthreads();

    // forward DFT at frequency k = t
    float xr = 0.f, xi = 0.f;
    int k = t;
    for (int tt = 0; tt < SEGD; tt++) {
        int id = (k * tt) & (SEGD - 1);
        float v = sx[tt];
        xr += v * twc[id];
        xi -= v * tws[id];
    }
    float fk = (k < 128) ? (float)k * (1.0f / 256.0f) : (float)(k - 256) * (1.0f / 256.0f);
    float sg = sigma[layer];
    float gk = expf(-fk * fk * sg * sg);
    float dgv = delta[((size_t)(b * LL + s0 + k)) * EDD + e];
    float w = 6.283185307179586f * fk * gk / (dgv + 1e-5f);
    Sre[k] = -w * xi;   // i*w*(xr+i*xi) = -w*xi + i*w*xr
    Sim[k] =  w * xr;
    __syncthreads();

    // inverse DFT (real part) at time t
    float acc = 0.f;
    for (int kk = 0; kk < SEGD; kk++) {
        int id = (kk * t) & (SEGD - 1);
        acc += Sre[kk] * twc[id] - Sim[kk] * tws[id];
    }
    acc *= (1.0f / 256.0f);
    size_t kid = ((size_t)(b * SEGD + t)) * EDD + e;
    Kdy[kid] = Kst[kid] * acc;
}

// ---------------- segment scan (h_t = a_t h_{t-1} + b_t) + y output ----------------
__global__ void scan_kernel(const float* __restrict__ xs, const float* __restrict__ delta,
                            const float* __restrict__ Cm, const float* __restrict__ Kst,
                            const float* __restrict__ Kdy, const float* __restrict__ Alog,
                            const float* __restrict__ Dp, float* __restrict__ y, int s0)
{
    __shared__ float sa0[SEGD], sb0[SEGD], sa1[SEGD], sb1[SEGD];
    int t = threadIdx.x;
    int be = blockIdx.x;
    int b = be >> 11, e = be & (EDD - 1);
    size_t rowL = ((size_t)(b * LL + s0 + t)) * EDD + e;
    size_t rowS = ((size_t)(b * SEGD + t)) * EDD + e;
    float xg  = xs[rowL];
    float dg  = delta[rowL];
    float kv  = Kst[rowS];
    float kdy = Kdy[rowS];
    float C0 = Cm[(size_t)(b * LL + s0 + t) * NSTD + 0];
    float C1 = Cm[(size_t)(b * LL + s0 + t) * NSTD + 1];
    float A0 = -expf(Alog[e * NSTD + 0]);
    float A1 = -expf(Alog[e * NSTD + 1]);

    float KC0 = kv * C0, KC1 = kv * C1;
    float AmK0 = A0 * (1.f - KC0), AmK1 = A1 * (1.f - KC1);
    float Ak0 = AmK0 * (1.f + KC0), Ak1 = AmK1 * (1.f + KC1);
    float Bk0 = -AmK0 * kv, Bk1 = -AmK1 * kv;
    float a0 = expf(dg * Ak0), a1 = expf(dg * Ak1);
    float b0 = dg * Bk0 * xg + kdy;
    float b1 = dg * Bk1 * xg + kdy;

    sa0[t] = a0; sb0[t] = b0; sa1[t] = a1; sb1[t] = b1;
    __syncthreads();
    for (int d = 1; d < SEGD; d <<= 1) {
        float pa0 = 0, pb0 = 0, pa1 = 0, pb1 = 0;
        if (t >= d) { pa0 = sa0[t - d]; pb0 = sb0[t - d]; pa1 = sa1[t - d]; pb1 = sb1[t - d]; }
        __syncthreads();
        if (t >= d) {
            sb0[t] = sa0[t] * pb0 + sb0[t];
            sa0[t] = sa0[t] * pa0;
            sb1[t] = sa1[t] * pb1 + sb1[t];
            sa1[t] = sa1[t] * pa1;
        }
        __syncthreads();
    }
    float h0 = sb0[t], h1 = sb1[t];
    y[rowL] = h0 * C0 + h1 * C1 + Dp[e] * xg;
}

// ---------------- gate: g = y * silu(z) ----------------
__global__ void gate_kernel(const float* __restrict__ y, const float* __restrict__ xz,
                            float* __restrict__ g)
{
    size_t idx = (size_t)blockIdx.x * blockDim.x + threadIdx.x;
    if (idx >= (size_t)MROWS * EDD) return;
    int e = (int)(idx & (EDD - 1));
    int m = (int)(idx >> 11);
    float z = xz[(size_t)m * (2 * EDD) + EDD + e];
    g[idx] = y[idx] * (z / (1.f + expf(-z)));
}

// ---------------- host driver ----------------
extern "C" void kernel_launch(void* const* d_in, const int* in_sizes, int n_in,
                              void* d_out, int out_size)
{
    const float* x      = (const float*)d_in[0];
    const float* rms_w  = (const float*)d_in[1];
    const float* in_w   = (const float*)d_in[2];
    const float* c1_w   = (const float*)d_in[3];
    const float* c1_b   = (const float*)d_in[4];
    const float* c2_w   = (const float*)d_in[5];
    const float* c2_b   = (const float*)d_in[6];
    const float* xp_w   = (const float*)d_in[7];
    const float* dt_w   = (const float*)d_in[8];
    const float* dt_b   = (const float*)d_in[9];
    const float* A_log  = (const float*)d_in[10];
    const float* Dp     = (const float*)d_in[11];
    const float* out_w  = (const float*)d_in[12];
    const float* k1_w   = (const float*)d_in[13];
    const float* k1_b   = (const float*)d_in[14];
    const float* k2_w   = (const float*)d_in[15];
    const float* k3_w   = (const float*)d_in[16];
    const float* ln_g   = (const float*)d_in[17];
    const float* ln_b   = (const float*)d_in[18];
    const float* k_alpha= (const float*)d_in[19];
    const float* sigma  = (const float*)d_in[20];
    float* h = (float*)d_out;

    float *xn, *xz, *xs, *dC, *dr, *Cm, *delta, *y, *gate, *K, *Kerr, *Kdy, *Knew, *h1, *h2;
    cudaGetSymbolAddress((void**)&xn,    g_xn);
    cudaGetSymbolAddress((void**)&xz,    g_xz);
    cudaGetSymbolAddress((void**)&xs,    g_xs);
    cudaGetSymbolAddress((void**)&dC,    g_dC);
    cudaGetSymbolAddress((void**)&dr,    g_dr);
    cudaGetSymbolAddress((void**)&Cm,    g_Cm);
    cudaGetSymbolAddress((void**)&delta, g_delta);
    cudaGetSymbolAddress((void**)&y,     g_y);
    cudaGetSymbolAddress((void**)&gate,  g_gate);
    cudaGetSymbolAddress((void**)&K,     g_K);
    cudaGetSymbolAddress((void**)&Kerr,  g_Kerr);
    cudaGetSymbolAddress((void**)&Kdy,   g_Kdy);
    cudaGetSymbolAddress((void**)&Knew,  g_Knew);
    cudaGetSymbolAddress((void**)&h1,    g_h1);
    cudaGetSymbolAddress((void**)&h2,    g_h2);

    // h = x (residual stream lives in d_out)
    cudaMemcpyAsync(h, x, (size_t)MROWS * DMD * sizeof(float), cudaMemcpyDeviceToDevice);

    for (int i = 0; i < 2; i++) {
        const float* in_wi  = in_w  + (size_t)i * 2 * EDD * DMD;
        const float* c1_wi  = c1_w  + (size_t)i * EDD * 2;
        const float* c1_bi  = c1_b  + (size_t)i * EDD;
        const float* c2_wi  = c2_w  + (size_t)i * EDD * 2;
        const float* c2_bi  = c2_b  + (size_t)i * EDD;
        const float* xp_wi  = xp_w  + (size_t)i * NCD * EDD;
        const float* dt_wi  = dt_w  + (size_t)i * EDD * DTRD;
        const float* dt_bi  = dt_b  + (size_t)i * EDD;
        const float* Alogi  = A_log + (size_t)i * EDD * NSTD;
        const float* Dpi    = Dp    + (size_t)i * EDD;
        const float* out_wi = out_w + (size_t)i * DMD * EDD;
        const float* k1_wi  = k1_w  + (size_t)i * 3 * EDD * EDD;
        const float* k1_bi  = k1_b  + (size_t)i * 3 * EDD;
        const float* k2_wi  = k2_w  + (size_t)i * EDD * 3 * EDD;
        const float* k3_wi  = k3_w  + (size_t)i * EDD * EDD;
        const float* ln_gi  = ln_g  + (size_t)i * EDD;
        const float* ln_bi  = ln_b  + (size_t)i * EDD;
        const float* kai    = k_alpha + (size_t)i * EDD;
        const float* rmsi   = rms_w + (size_t)i * DMD;

        rmsnorm_kernel<<<MROWS, 256>>>(h, rmsi, xn);

        gemm_tn<0><<<dim3(2 * EDD / 128, MROWS / 128), 256>>>(
            xn, in_wi, nullptr, xz, MROWS, 2 * EDD, DMD);

        conv_silu_kernel<<<(MROWS * EDD) / 256, 256>>>(xz, c1_wi, c1_bi, c2_wi, c2_bi, xs);

        gemm_tn<0><<<dim3(1, MROWS / 128), 256>>>(xs, xp_wi, nullptr, dC, MROWS, NCD, EDD);
        split_dC_kernel<<<(MROWS * NCD + 255) / 256, 256>>>(dC, dr, Cm);

        gemm_tn<3><<<dim3(EDD / 128, MROWS / 128), 256>>>(
            dr, dt_wi, dt_bi, delta, MROWS, EDD, DTRD);

        cudaMemsetAsync(K, 0, (size_t)MSEG * EDD * sizeof(float));

        for (int s = 0; s < NSEG; s++) {
            int s0 = s * SEGD;
            kerr_kernel<<<(MSEG * EDD) / 256, 256>>>(xs, y, Kerr, s0);
            gemm_tn<1><<<dim3(3 * EDD / 128, MSEG / 128), 256>>>(
                Kerr, k1_wi, k1_bi, h1, MSEG, 3 * EDD, EDD);
            gemm_tn<2><<<dim3(EDD / 128, MSEG / 128), 256>>>(
                h1, k2_wi, nullptr, h2, MSEG, EDD, 3 * EDD);
            gemm_tn<0><<<dim3(EDD / 128, MSEG / 128), 256>>>(
                h2, k3_wi, nullptr, Knew, MSEG, EDD, EDD);
            ln_kupdate_kernel<<<MSEG, 256>>>(Knew, ln_gi, ln_bi, kai, K);
            fdu_kernel<<<BB * EDD, SEGD>>>(xs, delta, K, Kdy, sigma, i, s0);
            scan_kernel<<<BB * EDD, SEGD>>>(xs, delta, Cm, K, Kdy, Alogi, Dpi, y, s0);
        }

        gate_kernel<<<(MROWS * EDD) / 256, 256>>>(y, xz, gate);
        gemm_tn<4><<<dim3(DMD / 128, MROWS / 128), 256>>>(
            gate, out_wi, nullptr, h, MROWS, DMD, EDD);
    }
}

// round 8
// speedup vs baseline: 1.3144x; 1.3144x over previous
#include <cuda_runtime.h>
#include <cuda_bf16.h>
#include <math.h>

typedef __nv_bfloat16 bf16;

// ---------------- problem constants ----------------
#define BB   4
#define LL   2048
#define DMD  1024
#define EDD  2048
#define SEGD 256
#define NSEG 8
#define DTRD 64
#define NSTD 2
#define NCD  66            // DTR + N
#define MROWS (BB*LL)      // 8192
#define MSEG  (BB*SEGD)    // 1024

// ---------------- scratch (device globals; no mallocs allowed) ----------------
__device__ float g_xz   [MROWS*2*EDD];
__device__ float g_xs   [MROWS*EDD];
__device__ float g_dC   [MROWS*NCD];
__device__ float g_dr   [MROWS*DTRD];
__device__ float g_Cm   [MROWS*NSTD];
__device__ float g_delta[MROWS*EDD];
__device__ float g_y    [MROWS*EDD];
__device__ float g_K    [MSEG*EDD];
__device__ float g_Knew [MSEG*EDD];

// bf16 hi/lo pairs for tensor-core path
__device__ bf16 g_xnh [MROWS*DMD];
__device__ bf16 g_xnl [MROWS*DMD];
__device__ bf16 g_gh  [MROWS*EDD];
__device__ bf16 g_gl  [MROWS*EDD];
__device__ bf16 g_keh [MSEG*EDD];
__device__ bf16 g_kel [MSEG*EDD];
__device__ bf16 g_h1h [MSEG*3*EDD];
__device__ bf16 g_h1l [MSEG*3*EDD];
__device__ bf16 g_h2h [MSEG*EDD];
__device__ bf16 g_h2l [MSEG*EDD];
__device__ bf16 g_wih [2*EDD*DMD];
__device__ bf16 g_wil [2*EDD*DMD];
__device__ bf16 g_woh [DMD*EDD];
__device__ bf16 g_wol [DMD*EDD];
__device__ bf16 g_w1h [3*EDD*EDD];
__device__ bf16 g_w1l [3*EDD*EDD];
__device__ bf16 g_w2h [3*EDD*EDD];
__device__ bf16 g_w2l [3*EDD*EDD];
__device__ bf16 g_w3h [EDD*EDD];
__device__ bf16 g_w3l [EDD*EDD];

// ---------------- bf16 split helper ----------------
__device__ __forceinline__ void bf16_split(float v, bf16& h, bf16& l) {
    h = __float2bfloat16(v);
    l = __float2bfloat16(v - __bfloat162float(h));
}

// ---------------- mma.sync m16n8k16 bf16 wrapper ----------------
__device__ __forceinline__ void mma_bf16(float* c, const unsigned* a, const unsigned* b) {
    asm volatile(
        "mma.sync.aligned.m16n8k16.row.col.f32.bf16.bf16.f32 "
        "{%0,%1,%2,%3}, {%4,%5,%6,%7}, {%8,%9}, {%0,%1,%2,%3};\n"
        : "+f"(c[0]), "+f"(c[1]), "+f"(c[2]), "+f"(c[3])
        : "r"(a[0]), "r"(a[1]), "r"(a[2]), "r"(a[3]), "r"(b[0]), "r"(b[1]));
}

// ---------------- tensor-core GEMM: C[M,N] = (Ah+Al)[M,K] @ (Bh+Bl)[N,K]^T ----------------
// 3-pass bf16 split (hh + hl + lh). fp32 accumulate.
// EPI: 0 fp32 out; 1 bias+relu -> bf16 hi/lo; 2 relu -> bf16 hi/lo; 4 fp32 accumulate (Cf += v)
// Requires M%128==0, N%128==0, K%16==0.
#define SPAD 20
template<int EPI>
__global__ __launch_bounds__(256) void gemm_bf3(
    const bf16* __restrict__ Ah, const bf16* __restrict__ Al,
    const bf16* __restrict__ Bh, const bf16* __restrict__ Bl,
    const float* __restrict__ bias,
    bf16* __restrict__ Ch, bf16* __restrict__ Cl, float* __restrict__ Cf,
    int M, int N, int K)
{
    __shared__ __align__(16) bf16 sAh[2][128][SPAD];
    __shared__ __align__(16) bf16 sAl[2][128][SPAD];
    __shared__ __align__(16) bf16 sBh[2][128][SPAD];
    __shared__ __align__(16) bf16 sBl[2][128][SPAD];

    const int tid = threadIdx.x;
    const int m0 = blockIdx.y * 128;
    const int n0 = blockIdx.x * 128;
    const int wid = tid >> 5, lane = tid & 31;
    const int wm = wid & 3;
    const int wn = wid >> 2;
    const int lr = lane >> 2, lc = lane & 3;

    float acc[2][8][4];
#pragma unroll
    for (int tm = 0; tm < 2; tm++)
#pragma unroll
        for (int tn = 0; tn < 8; tn++)
#pragma unroll
            for (int q = 0; q < 4; q++) acc[tm][tn][q] = 0.f;

    const int lrow0 = tid >> 2;
    const int lq    = tid & 3;

    // prologue: stage 0
#pragma unroll
    for (int i = 0; i < 2; i++) {
        int row = lrow0 + i * 64;
        *(uint2*)(&sAh[0][row][lq * 4]) = *(const uint2*)(Ah + (size_t)(m0 + row) * K + lq * 4);
        *(uint2*)(&sAl[0][row][lq * 4]) = *(const uint2*)(Al + (size_t)(m0 + row) * K + lq * 4);
        *(uint2*)(&sBh[0][row][lq * 4]) = *(const uint2*)(Bh + (size_t)(n0 + row) * K + lq * 4);
        *(uint2*)(&sBl[0][row][lq * 4]) = *(const uint2*)(Bl + (size_t)(n0 + row) * K + lq * 4);
    }
    __syncthreads();

    int buf = 0;
    for (int k0 = 0; k0 < K; k0 += 16) {
        const bool more = (k0 + 16) < K;
        uint2 pf[4][2];
        if (more) {
#pragma unroll
            for (int i = 0; i < 2; i++) {
                int row = lrow0 + i * 64;
                size_t ka = (size_t)(m0 + row) * K + k0 + 16 + lq * 4;
                size_t kb = (size_t)(n0 + row) * K + k0 + 16 + lq * 4;
                pf[0][i] = *(const uint2*)(Ah + ka);
                pf[1][i] = *(const uint2*)(Al + ka);
                pf[2][i] = *(const uint2*)(Bh + kb);
                pf[3][i] = *(const uint2*)(Bl + kb);
            }
        }

        unsigned ah[2][4], al[2][4], bh[8][2], bl[8][2];
#pragma unroll
        for (int tm = 0; tm < 2; tm++) {
            int r = wm * 32 + tm * 16 + lr;
            ah[tm][0] = *(const unsigned*)(&sAh[buf][r    ][lc * 2]);
            ah[tm][1] = *(const unsigned*)(&sAh[buf][r + 8][lc * 2]);
            ah[tm][2] = *(const unsigned*)(&sAh[buf][r    ][lc * 2 + 8]);
            ah[tm][3] = *(const unsigned*)(&sAh[buf][r + 8][lc * 2 + 8]);
            al[tm][0] = *(const unsigned*)(&sAl[buf][r    ][lc * 2]);
            al[tm][1] = *(const unsigned*)(&sAl[buf][r + 8][lc * 2]);
            al[tm][2] = *(const unsigned*)(&sAl[buf][r    ][lc * 2 + 8]);
            al[tm][3] = *(const unsigned*)(&sAl[buf][r + 8][lc * 2 + 8]);
        }
#pragma unroll
        for (int tn = 0; tn < 8; tn++) {
            int r = wn * 64 + tn * 8 + lr;
            bh[tn][0] = *(const unsigned*)(&sBh[buf][r][lc * 2]);
            bh[tn][1] = *(const unsigned*)(&sBh[buf][r][lc * 2 + 8]);
            bl[tn][0] = *(const unsigned*)(&sBl[buf][r][lc * 2]);
            bl[tn][1] = *(const unsigned*)(&sBl[buf][r][lc * 2 + 8]);
        }

        // 3 passes: hi*hi, hi*lo, lo*hi
#pragma unroll
        for (int tm = 0; tm < 2; tm++)
#pragma unroll
            for (int tn = 0; tn < 8; tn++)
                mma_bf16(acc[tm][tn], ah[tm], bh[tn]);
#pragma unroll
        for (int tm = 0; tm < 2; tm++)
#pragma unroll
            for (int tn = 0; tn < 8; tn++)
                mma_bf16(acc[tm][tn], ah[tm], bl[tn]);
#pragma unroll
        for (int tm = 0; tm < 2; tm++)
#pragma unroll
            for (int tn = 0; tn < 8; tn++)
                mma_bf16(acc[tm][tn], al[tm], bh[tn]);

        __syncthreads();
        if (more) {
            int nb = buf ^ 1;
#pragma unroll
            for (int i = 0; i < 2; i++) {
                int row = lrow0 + i * 64;
                *(uint2*)(&sAh[nb][row][lq * 4]) = pf[0][i];
                *(uint2*)(&sAl[nb][row][lq * 4]) = pf[1][i];
                *(uint2*)(&sBh[nb][row][lq * 4]) = pf[2][i];
                *(uint2*)(&sBl[nb][row][lq * 4]) = pf[3][i];
            }
            __syncthreads();
            buf = nb;
        }
    }

    // epilogue
#pragma unroll
    for (int tm = 0; tm < 2; tm++) {
#pragma unroll
        for (int tn = 0; tn < 8; tn++) {
            int row = m0 + wm * 32 + tm * 16 + lr;
            int col = n0 + wn * 64 + tn * 8 + lc * 2;
            const float* a = acc[tm][tn];
#pragma unroll
            for (int q = 0; q < 4; q++) {
                int r = row + (q >> 1) * 8;
                int c = col + (q & 1);
                float v = a[q];
                size_t idx = (size_t)r * N + c;
                if (EPI == 0) {
                    Cf[idx] = v;
                } else if (EPI == 4) {
                    Cf[idx] += v;
                } else {
                    if (EPI == 1) v += bias[c];
                    v = fmaxf(v, 0.f);
                    bf16 h, l; bf16_split(v, h, l);
                    Ch[idx] = h; Cl[idx] = l;
                }
            }
        }
    }
}

// ---------------- weight split: fp32 -> bf16 hi/lo ----------------
__global__ void split_w_kernel(const float* __restrict__ w,
                               bf16* __restrict__ wh, bf16* __restrict__ wl, int n)
{
    int i = blockIdx.x * 256 + threadIdx.x;
    if (i < n) {
        bf16 h, l; bf16_split(w[i], h, l);
        wh[i] = h; wl[i] = l;
    }
}

// ---------------- generic fp32 GEMM: C[M,N] = A[M,K] @ B[N,K]^T ----------------
// EPI: 0 none, 3 bias+softplus
template<int EPI>
__global__ __launch_bounds__(256) void gemm_tn(
    const float* __restrict__ A, const float* __restrict__ Bw,
    const float* __restrict__ bias, float* __restrict__ C,
    int M, int N, int K)
{
    __shared__ float As[2][16][128];
    __shared__ float Bs[2][16][128];
    const int tid = threadIdx.x;
    const int m0 = blockIdx.y * 128;
    const int n0 = blockIdx.x * 128;
    const int tx = tid & 15;
    const int ty = tid >> 4;

    float acc[8][8];
#pragma unroll
    for (int i = 0; i < 8; i++)
#pragma unroll
        for (int j = 0; j < 8; j++) acc[i][j] = 0.f;

    const int lrow = tid >> 1;
    const int lcol = (tid & 1) * 8;
    const float* Aptr = A + (size_t)(m0 + lrow) * K + lcol;
    const bool bvalid = (n0 + lrow) < N;
    const float* Bptr = Bw + (size_t)(n0 + lrow) * K + lcol;

    {
        float4 a0 = *(const float4*)(Aptr);
        float4 a1 = *(const float4*)(Aptr + 4);
        float4 b0 = make_float4(0.f, 0.f, 0.f, 0.f);
        float4 b1 = make_float4(0.f, 0.f, 0.f, 0.f);
        if (bvalid) {
            b0 = *(const float4*)(Bptr);
            b1 = *(const float4*)(Bptr + 4);
        }
        As[0][lcol + 0][lrow] = a0.x; As[0][lcol + 1][lrow] = a0.y;
        As[0][lcol + 2][lrow] = a0.z; As[0][lcol + 3][lrow] = a0.w;
        As[0][lcol + 4][lrow] = a1.x; As[0][lcol + 5][lrow] = a1.y;
        As[0][lcol + 6][lrow] = a1.z; As[0][lcol + 7][lrow] = a1.w;
        Bs[0][lcol + 0][lrow] = b0.x; Bs[0][lcol + 1][lrow] = b0.y;
        Bs[0][lcol + 2][lrow] = b0.z; Bs[0][lcol + 3][lrow] = b0.w;
        Bs[0][lcol + 4][lrow] = b1.x; Bs[0][lcol + 5][lrow] = b1.y;
        Bs[0][lcol + 6][lrow] = b1.z; Bs[0][lcol + 7][lrow] = b1.w;
    }
    __syncthreads();

    int nbuf = 1;
    for (int k0 = 0; k0 < K; k0 += 16) {
        const int cur = nbuf ^ 1;
        const bool more = (k0 + 16) < K;

        float4 a0, a1, b0, b1;
        if (more) {
            a0 = *(const float4*)(Aptr + k0 + 16);
            a1 = *(const float4*)(Aptr + k0 + 20);
            b0 = make_float4(0.f, 0.f, 0.f, 0.f);
            b1 = make_float4(0.f, 0.f, 0.f, 0.f);
            if (bvalid) {
                b0 = *(const float4*)(Bptr + k0 + 16);
                b1 = *(const float4*)(Bptr + k0 + 20);
            }
        }

#pragma unroll
        for (int kk = 0; kk < 16; kk++) {
            float ra[8], rb[8];
            *(float4*)(ra)     = *(const float4*)(&As[cur][kk][ty * 8]);
            *(float4*)(ra + 4) = *(const float4*)(&As[cur][kk][ty * 8 + 4]);
            *(float4*)(rb)     = *(const float4*)(&Bs[cur][kk][tx * 8]);
            *(float4*)(rb + 4) = *(const float4*)(&Bs[cur][kk][tx * 8 + 4]);
#pragma unroll
            for (int i = 0; i < 8; i++)
#pragma unroll
                for (int j = 0; j < 8; j++)
                    acc[i][j] = fmaf(ra[i], rb[j], acc[i][j]);
        }
        __syncthreads();

        if (more) {
            As[nbuf][lcol + 0][lrow] = a0.x; As[nbuf][lcol + 1][lrow] = a0.y;
            As[nbuf][lcol + 2][lrow] = a0.z; As[nbuf][lcol + 3][lrow] = a0.w;
            As[nbuf][lcol + 4][lrow] = a1.x; As[nbuf][lcol + 5][lrow] = a1.y;
            As[nbuf][lcol + 6][lrow] = a1.z; As[nbuf][lcol + 7][lrow] = a1.w;
            Bs[nbuf][lcol + 0][lrow] = b0.x; Bs[nbuf][lcol + 1][lrow] = b0.y;
            Bs[nbuf][lcol + 2][lrow] = b0.z; Bs[nbuf][lcol + 3][lrow] = b0.w;
            Bs[nbuf][lcol + 4][lrow] = b1.x; Bs[nbuf][lcol + 5][lrow] = b1.y;
            Bs[nbuf][lcol + 6][lrow] = b1.z; Bs[nbuf][lcol + 7][lrow] = b1.w;
            __syncthreads();
            nbuf ^= 1;
        }
    }

    const int mbase = m0 + ty * 8;
    const int nbase = n0 + tx * 8;
#pragma unroll
    for (int i = 0; i < 8; i++) {
#pragma unroll
        for (int j = 0; j < 8; j++) {
            int n = nbase + j;
            if (n >= N) continue;
            size_t idx = (size_t)(mbase + i) * N + n;
            float v = acc[i][j];
            if (EPI == 0) {
                C[idx] = v;
            } else { // 3
                float u = v + bias[n];
                C[idx] = (u > 15.f) ? u : log1pf(expf(u));
            }
        }
    }
}

// ---------------- RMSNorm over last dim DM -> bf16 hi/lo ----------------
__global__ void rmsnorm_kernel(const float* __restrict__ h,
                               const float* __restrict__ w,
                               bf16* __restrict__ oh, bf16* __restrict__ ol)
{
    __shared__ float red[256];
    int row = blockIdx.x;
    const float* hr = h + (size_t)row * DMD;
    float s = 0.f;
    for (int j = threadIdx.x; j < DMD; j += 256) { float v = hr[j]; s += v * v; }
    red[threadIdx.x] = s; __syncthreads();
    for (int o = 128; o > 0; o >>= 1) {
        if (threadIdx.x < o) red[threadIdx.x] += red[threadIdx.x + o];
        __syncthreads();
    }
    float scale = rsqrtf(red[0] * (1.f / DMD) + 1e-5f);
    for (int j = threadIdx.x; j < DMD; j += 256) {
        float v = hr[j] * scale * w[j];
        bf16 hh, ll; bf16_split(v, hh, ll);
        size_t id = (size_t)row * DMD + j;
        oh[id] = hh; ol[id] = ll;
    }
}

// ---------------- fused 2x depthwise conv (DCONV=2, causal) + SiLU ----------------
__global__ void conv_silu_kernel(const float* __restrict__ xz,
                                 const float* __restrict__ c1w, const float* __restrict__ c1b,
                                 const float* __restrict__ c2w, const float* __restrict__ c2b,
                                 float* __restrict__ xs)
{
    size_t idx = (size_t)blockIdx.x * blockDim.x + threadIdx.x;
    if (idx >= (size_t)MROWS * EDD) return;
    int e  = (int)(idx & (EDD - 1));
    int bl = (int)(idx >> 11);
    int l  = bl & (LL - 1);
    float x0  = xz[(size_t)bl * (2 * EDD) + e];
    float xm1 = (l >= 1) ? xz[(size_t)(bl - 1) * (2 * EDD) + e] : 0.f;
    float xm2 = (l >= 2) ? xz[(size_t)(bl - 2) * (2 * EDD) + e] : 0.f;
    float w10 = c1w[e * 2 + 0], w11 = c1w[e * 2 + 1], b1 = c1b[e];
    float w20 = c2w[e * 2 + 0], w21 = c2w[e * 2 + 1], b2 = c2b[e];
    float t1l   = b1 + w10 * xm1 + w11 * x0;
    float t1lm1 = (l >= 1) ? (b1 + w10 * xm2 + w11 * xm1) : 0.f;
    float u = b2 + w20 * t1lm1 + w21 * t1l;
    xs[idx] = u / (1.f + expf(-u));
}

// ---------------- split dC into dr (cols<64) and C (cols 64..65) ----------------
__global__ void split_dC_kernel(const float* __restrict__ dC,
                                float* __restrict__ dr, float* __restrict__ Cm)
{
    int idx = blockIdx.x * blockDim.x + threadIdx.x;
    if (idx >= MROWS * NCD) return;
    int m = idx / NCD, c = idx % NCD;
    float v = dC[idx];
    if (c < DTRD) dr[m * DTRD + c] = v;
    else          Cm[m * NSTD + (c - DTRD)] = v;
}

// ---------------- Kerr = softsign((xg - yh)^2) -> bf16 hi/lo ----------------
__global__ void kerr_kernel(const float* __restrict__ xs,
                            const float* __restrict__ y,
                            bf16* __restrict__ keh, bf16* __restrict__ kel, int s0)
{
    size_t idx = (size_t)blockIdx.x * blockDim.x + threadIdx.x;
    if (idx >= (size_t)MSEG * EDD) return;
    int e  = (int)(idx & (EDD - 1));
    int bt = (int)(idx >> 11);
    int t = bt & (SEGD - 1);
    int b = bt >> 8;
    size_t src = ((size_t)(b * LL + s0 + t)) * EDD + e;
    float xg = xs[src];
    float yh = (s0 > 0) ? y[((size_t)(b * LL + s0 - SEGD + t)) * EDD + e] : 0.f;
    float d = xg - yh;
    float u = d * d;
    float v = u / (1.f + u);
    bf16 h, l; bf16_split(v, h, l);
    keh[idx] = h; kel[idx] = l;
}

// ---------------- LayerNorm(Knew) + EMA update of K ----------------
__global__ void ln_kupdate_kernel(const float* __restrict__ Kn,
                                  const float* __restrict__ lng, const float* __restrict__ lnb,
                                  const float* __restrict__ ka, float* __restrict__ Kst)
{
    __shared__ float srow[EDD];
    __shared__ float red[256];
    int row = blockIdx.x;
    int tid = threadIdx.x;
    const float* hr = Kn + (size_t)row * EDD;
    float s = 0.f;
    for (int j = tid; j < EDD; j += 256) { float v = hr[j]; srow[j] = v; s += v; }
    red[tid] = s; __syncthreads();
    for (int o = 128; o > 0; o >>= 1) {
        if (tid < o) red[tid] += red[tid + o];
        __syncthreads();
    }
    float mu = red[0] * (1.f / EDD);
    __syncthreads();
    float s2 = 0.f;
    for (int j = tid; j < EDD; j += 256) { float d = srow[j] - mu; s2 += d * d; }
    red[tid] = s2; __syncthreads();
    for (int o = 128; o > 0; o >>= 1) {
        if (tid < o) red[tid] += red[tid + o];
        __syncthreads();
    }
    float rstd = rsqrtf(red[0] * (1.f / EDD) + 1e-5f);
    for (int j = tid; j < EDD; j += 256) {
        float o = lng[j] * (srow[j] - mu) * rstd + lnb[j];
        float a = fminf(fmaxf(ka[j], 0.01f), 0.99f);
        size_t id = (size_t)row * EDD + j;
        Kst[id] = (1.f - a) * Kst[id] + a * o;
    }
}

// ---------------- fused FDU (DFT filter) + segment scan + y output ----------------
// Thread t serves BOTH frequency index t (filter uses delta[b,s0+t,e]) and
// time index t (scan) — the reference's omega uses dt at the frequency index,
// so the single delta load is correct for both uses.
__global__ void fdu_scan_kernel(const float* __restrict__ xs,
                                const float* __restrict__ delta,
                                const float* __restrict__ Cm,
                                const float* __restrict__ Kst,
                                const float* __restrict__ Alog,
                                const float* __restrict__ Dp,
                                const float* __restrict__ sigma,
                                int layer, int s0,
                                float* __restrict__ y)
{
    __shared__ float  sx[SEGD];
    __shared__ float2 stw[SEGD];    // (cos, sin) twiddles
    __shared__ float2 sS[SEGD];     // filtered spectrum (re, im)
    __shared__ float sa0[SEGD], sb0[SEGD], sa1[SEGD], sb1[SEGD];

    int t = threadIdx.x;
    int be = blockIdx.x;
    int b = be >> 11, e = be & (EDD - 1);
    size_t rowL = ((size_t)(b * LL + s0 + t)) * EDD + e;
    size_t rowS = ((size_t)(b * SEGD + t)) * EDD + e;

    float cc, ss;
    sincospif((float)t * (1.0f / 128.0f), &ss, &cc);   // angle 2*pi*t/256
    stw[t] = make_float2(cc, ss);
    float xg = xs[rowL];
    float dg = delta[rowL];
    float kv = Kst[rowS];
    sx[t] = xg;
    __syncthreads();

    // forward DFT at frequency k = t
    float xr = 0.f, xi = 0.f;
    for (int tt = 0; tt < SEGD; tt++) {
        int id = (t * tt) & (SEGD - 1);
        float2 w2 = stw[id];
        float v = sx[tt];
        xr += v * w2.x;
        xi -= v * w2.y;
    }
    float fk = (t < 128) ? (float)t * (1.0f / 256.0f) : (float)(t - 256) * (1.0f / 256.0f);
    float sg = sigma[layer];
    float gk = expf(-fk * fk * sg * sg);
    float w = 6.283185307179586f * fk * gk / (dg + 1e-5f);
    sS[t] = make_float2(-w * xi, w * xr);   // i*w*(xr+i*xi)
    __syncthreads();

    // inverse DFT (real part) at time t
    float acc = 0.f;
    for (int kk = 0; kk < SEGD; kk++) {
        int id = (kk * t) & (SEGD - 1);
        float2 S = sS[kk];
        float2 w2 = stw[id];
        acc += S.x * w2.x - S.y * w2.y;
    }
    acc *= (1.0f / 256.0f);
    float kdy = kv * acc;

    // ----- scan -----
    float C0 = Cm[(size_t)(b * LL + s0 + t) * NSTD + 0];
    float C1 = Cm[(size_t)(b * LL + s0 + t) * NSTD + 1];
    float A0 = -expf(Alog[e * NSTD + 0]);
    float A1 = -expf(Alog[e * NSTD + 1]);

    float KC0 = kv * C0, KC1 = kv * C1;
    float AmK0 = A0 * (1.f - KC0), AmK1 = A1 * (1.f - KC1);
    float Ak0 = AmK0 * (1.f + KC0), Ak1 = AmK1 * (1.f + KC1);
    float Bk0 = -AmK0 * kv, Bk1 = -AmK1 * kv;
    float a0 = expf(dg * Ak0), a1 = expf(dg * Ak1);
    float b0 = dg * Bk0 * xg + kdy;
    float b1 = dg * Bk1 * xg + kdy;

    sa0[t] = a0; sb0[t] = b0; sa1[t] = a1; sb1[t] = b1;
    __syncthreads();
    for (int d = 1; d < SEGD; d <<= 1) {
        float pa0 = 0, pb0 = 0, pa1 = 0, pb1 = 0;
        if (t >= d) { pa0 = sa0[t - d]; pb0 = sb0[t - d]; pa1 = sa1[t - d]; pb1 = sb1[t - d]; }
        __syncthreads();
        if (t >= d) {
            sb0[t] = sa0[t] * pb0 + sb0[t];
            sa0[t] = sa0[t] * pa0;
            sb1[t] = sa1[t] * pb1 + sb1[t];
            sa1[t] = sa1[t] * pa1;
        }
        __syncthreads();
    }
    float h0 = sb0[t], h1 = sb1[t];
    y[rowL] = h0 * C0 + h1 * C1 + Dp[e] * xg;
}

// ---------------- gate: g = y * silu(z) -> bf16 hi/lo ----------------
__global__ void gate_kernel(const float* __restrict__ y, const float* __restrict__ xz,
                            bf16* __restrict__ gh, bf16* __restrict__ gl)
{
    size_t idx = (size_t)blockIdx.x * blockDim.x + threadIdx.x;
    if (idx >= (size_t)MROWS * EDD) return;
    int e = (int)(idx & (EDD - 1));
    int m = (int)(idx >> 11);
    float z = xz[(size_t)m * (2 * EDD) + EDD + e];
    float v = y[idx] * (z / (1.f + expf(-z)));
    bf16 h, l; bf16_split(v, h, l);
    gh[idx] = h; gl[idx] = l;
}

// ---------------- host driver ----------------
extern "C" void kernel_launch(void* const* d_in, const int* in_sizes, int n_in,
                              void* d_out, int out_size)
{
    const float* x      = (const float*)d_in[0];
    const float* rms_w  = (const float*)d_in[1];
    const float* in_w   = (const float*)d_in[2];
    const float* c1_w   = (const float*)d_in[3];
    const float* c1_b   = (const float*)d_in[4];
    const float* c2_w   = (const float*)d_in[5];
    const float* c2_b   = (const float*)d_in[6];
    const float* xp_w   = (const float*)d_in[7];
    const float* dt_w   = (const float*)d_in[8];
    const float* dt_b   = (const float*)d_in[9];
    const float* A_log  = (const float*)d_in[10];
    const float* Dp     = (const float*)d_in[11];
    const float* out_w  = (const float*)d_in[12];
    const float* k1_w   = (const float*)d_in[13];
    const float* k1_b   = (const float*)d_in[14];
    const float* k2_w   = (const float*)d_in[15];
    const float* k3_w   = (const float*)d_in[16];
    const float* ln_g   = (const float*)d_in[17];
    const float* ln_b   = (const float*)d_in[18];
    const float* k_alpha= (const float*)d_in[19];
    const float* sigma  = (const float*)d_in[20];
    float* h = (float*)d_out;

    float *xz, *xs, *dC, *dr, *Cm, *delta, *y, *K, *Knew;
    bf16 *xnh, *xnl, *gh, *gl, *keh, *kel, *h1h, *h1l, *h2h, *h2l;
    bf16 *wih, *wil, *woh, *wol, *w1h, *w1l, *w2h, *w2l, *w3h, *w3l;
    cudaGetSymbolAddress((void**)&xz,    g_xz);
    cudaGetSymbolAddress((void**)&xs,    g_xs);
    cudaGetSymbolAddress((void**)&dC,    g_dC);
    cudaGetSymbolAddress((void**)&dr,    g_dr);
    cudaGetSymbolAddress((void**)&Cm,    g_Cm);
    cudaGetSymbolAddress((void**)&delta, g_delta);
    cudaGetSymbolAddress((void**)&y,     g_y);
    cudaGetSymbolAddress((void**)&K,     g_K);
    cudaGetSymbolAddress((void**)&Knew,  g_Knew);
    cudaGetSymbolAddress((void**)&xnh,   g_xnh);
    cudaGetSymbolAddress((void**)&xnl,   g_xnl);
    cudaGetSymbolAddress((void**)&gh,    g_gh);
    cudaGetSymbolAddress((void**)&gl,    g_gl);
    cudaGetSymbolAddress((void**)&keh,   g_keh);
    cudaGetSymbolAddress((void**)&kel,   g_kel);
    cudaGetSymbolAddress((void**)&h1h,   g_h1h);
    cudaGetSymbolAddress((void**)&h1l,   g_h1l);
    cudaGetSymbolAddress((void**)&h2h,   g_h2h);
    cudaGetSymbolAddress((void**)&h2l,   g_h2l);
    cudaGetSymbolAddress((void**)&wih,   g_wih);
    cudaGetSymbolAddress((void**)&wil,   g_wil);
    cudaGetSymbolAddress((void**)&woh,   g_woh);
    cudaGetSymbolAddress((void**)&wol,   g_wol);
    cudaGetSymbolAddress((void**)&w1h,   g_w1h);
    cudaGetSymbolAddress((void**)&w1l,   g_w1l);
    cudaGetSymbolAddress((void**)&w2h,   g_w2h);
    cudaGetSymbolAddress((void**)&w2l,   g_w2l);
    cudaGetSymbolAddress((void**)&w3h,   g_w3h);
    cudaGetSymbolAddress((void**)&w3l,   g_w3l);

    cudaMemcpyAsync(h, x, (size_t)MROWS * DMD * sizeof(float), cudaMemcpyDeviceToDevice);

    for (int i = 0; i < 2; i++) {
        const float* in_wi  = in_w  + (size_t)i * 2 * EDD * DMD;
        const float* c1_wi  = c1_w  + (size_t)i * EDD * 2;
        const float* c1_bi  = c1_b  + (size_t)i * EDD;
        const float* c2_wi  = c2_w  + (size_t)i * EDD * 2;
        const float* c2_bi  = c2_b  + (size_t)i * EDD;
        const float* xp_wi  = xp_w  + (size_t)i * NCD * EDD;
        const float* dt_wi  = dt_w  + (size_t)i * EDD * DTRD;
        const float* dt_bi  = dt_b  + (size_t)i * EDD;
        const float* Alogi  = A_log + (size_t)i * EDD * NSTD;
        const float* Dpi    = Dp    + (size_t)i * EDD;
        const float* out_wi = out_w + (size_t)i * DMD * EDD;
        const float* k1_wi  = k1_w  + (size_t)i * 3 * EDD * EDD;
        const float* k1_bi  = k1_b  + (size_t)i * 3 * EDD;
        const float* k2_wi  = k2_w  + (size_t)i * EDD * 3 * EDD;
        const float* k3_wi  = k3_w  + (size_t)i * EDD * EDD;
        const float* ln_gi  = ln_g  + (size_t)i * EDD;
        const float* ln_bi  = ln_b  + (size_t)i * EDD;
        const float* kai    = k_alpha + (size_t)i * EDD;
        const float* rmsi   = rms_w + (size_t)i * DMD;

        // weight splits for this layer's tensor-core GEMMs
        split_w_kernel<<<(2 * EDD * DMD + 255) / 256, 256>>>(in_wi, wih, wil, 2 * EDD * DMD);
        split_w_kernel<<<(DMD * EDD + 255) / 256, 256>>>(out_wi, woh, wol, DMD * EDD);
        split_w_kernel<<<(3 * EDD * EDD + 255) / 256, 256>>>(k1_wi, w1h, w1l, 3 * EDD * EDD);
        split_w_kernel<<<(3 * EDD * EDD + 255) / 256, 256>>>(k2_wi, w2h, w2l, 3 * EDD * EDD);
        split_w_kernel<<<(EDD * EDD + 255) / 256, 256>>>(k3_wi, w3h, w3l, EDD * EDD);

        rmsnorm_kernel<<<MROWS, 256>>>(h, rmsi, xnh, xnl);

        // in-proj: xz = xn @ in_w^T  (tensor cores)
        gemm_bf3<0><<<dim3(2 * EDD / 128, MROWS / 128), 256>>>(
            xnh, xnl, wih, wil, nullptr, nullptr, nullptr, xz, MROWS, 2 * EDD, DMD);

        conv_silu_kernel<<<(MROWS * EDD) / 256, 256>>>(xz, c1_wi, c1_bi, c2_wi, c2_bi, xs);

        gemm_tn<0><<<dim3(1, MROWS / 128), 256>>>(xs, xp_wi, nullptr, dC, MROWS, NCD, EDD);
        split_dC_kernel<<<(MROWS * NCD + 255) / 256, 256>>>(dC, dr, Cm);

        gemm_tn<3><<<dim3(EDD / 128, MROWS / 128), 256>>>(
            dr, dt_wi, dt_bi, delta, MROWS, EDD, DTRD);

        cudaMemsetAsync(K, 0, (size_t)MSEG * EDD * sizeof(float));

        for (int s = 0; s < NSEG; s++) {
            int s0 = s * SEGD;
            kerr_kernel<<<(MSEG * EDD) / 256, 256>>>(xs, y, keh, kel, s0);
            gemm_bf3<1><<<dim3(3 * EDD / 128, MSEG / 128), 256>>>(
                keh, kel, w1h, w1l, k1_bi, h1h, h1l, nullptr, MSEG, 3 * EDD, EDD);
            gemm_bf3<2><<<dim3(EDD / 128, MSEG / 128), 256>>>(
                h1h, h1l, w2h, w2l, nullptr, h2h, h2l, nullptr, MSEG, EDD, 3 * EDD);
            gemm_bf3<0><<<dim3(EDD / 128, MSEG / 128), 256>>>(
                h2h, h2l, w3h, w3l, nullptr, nullptr, nullptr, Knew, MSEG, EDD, EDD);
            ln_kupdate_kernel<<<MSEG, 256>>>(Knew, ln_gi, ln_bi, kai, K);
            fdu_scan_kernel<<<BB * EDD, SEGD>>>(xs, delta, Cm, K, Alogi, Dpi, sigma, i, s0, y);
        }

        gate_kernel<<<(MROWS * EDD) / 256, 256>>>(y, xz, gh, gl);
        // out-proj: h += gate @ out_w^T  (tensor cores, accumulate)
        gemm_bf3<4><<<dim3(DMD / 128, MROWS / 128), 256>>>(
            gh, gl, woh, wol, nullptr, nullptr, nullptr, h, MROWS, DMD, EDD);
    }
}

// round 15
// speedup vs baseline: 1.7004x; 1.2937x over previous
#include <cuda_runtime.h>
#include <cuda_bf16.h>
#include <math.h>

typedef __nv_bfloat16 bf16;

// ---------------- problem constants ----------------
#define BB   4
#define LL   2048
#define DMD  1024
#define EDD  2048
#define SEGD 256
#define NSEG 8
#define DTRD 64
#define NSTD 2
#define NCD  66            // DTR + N
#define MROWS (BB*LL)      // 8192
#define MSEG  (BB*SEGD)    // 1024

// ---------------- scratch (device globals; no mallocs allowed) ----------------
__device__ float g_xz   [MROWS*2*EDD];
__device__ float g_xs   [MROWS*EDD];
__device__ float g_dC   [MROWS*NCD];
__device__ float g_dr   [MROWS*DTRD];
__device__ float g_Cm   [MROWS*NSTD];
__device__ float g_delta[MROWS*EDD];
__device__ float g_y    [MROWS*EDD];
__device__ float g_K    [MSEG*EDD];
__device__ float g_Knew [MSEG*EDD];

// bf16 hi/lo pairs for tensor-core path
__device__ bf16 g_xnh [MROWS*DMD];
__device__ bf16 g_xnl [MROWS*DMD];
__device__ bf16 g_gh  [MROWS*EDD];
__device__ bf16 g_gl  [MROWS*EDD];
__device__ bf16 g_keh [MSEG*EDD];
__device__ bf16 g_kel [MSEG*EDD];
__device__ bf16 g_h1h [MSEG*3*EDD];
__device__ bf16 g_h1l [MSEG*3*EDD];
__device__ bf16 g_h2h [MSEG*EDD];
__device__ bf16 g_h2l [MSEG*EDD];
__device__ bf16 g_wih [2*EDD*DMD];
__device__ bf16 g_wil [2*EDD*DMD];
__device__ bf16 g_woh [DMD*EDD];
__device__ bf16 g_wol [DMD*EDD];
__device__ bf16 g_w1h [3*EDD*EDD];
__device__ bf16 g_w1l [3*EDD*EDD];
__device__ bf16 g_w2h [3*EDD*EDD];
__device__ bf16 g_w2l [3*EDD*EDD];
__device__ bf16 g_w3h [EDD*EDD];
__device__ bf16 g_w3l [EDD*EDD];

// ---------------- bf16 split helper ----------------
__device__ __forceinline__ void bf16_split(float v, bf16& h, bf16& l) {
    h = __float2bfloat16(v);
    l = __float2bfloat16(v - __bfloat162float(h));
}

// ---------------- mma.sync m16n8k16 bf16 wrapper ----------------
__device__ __forceinline__ void mma_bf16(float* c, const unsigned* a, const unsigned* b) {
    asm volatile(
        "mma.sync.aligned.m16n8k16.row.col.f32.bf16.bf16.f32 "
        "{%0,%1,%2,%3}, {%4,%5,%6,%7}, {%8,%9}, {%0,%1,%2,%3};\n"
        : "+f"(c[0]), "+f"(c[1]), "+f"(c[2]), "+f"(c[3])
        : "r"(a[0]), "r"(a[1]), "r"(a[2]), "r"(a[3]), "r"(b[0]), "r"(b[1]));
}

__device__ __forceinline__ void ldsm_x4(unsigned& r0, unsigned& r1, unsigned& r2, unsigned& r3,
                                        const bf16* p) {
    unsigned addr = (unsigned)__cvta_generic_to_shared(p);
    asm volatile("ldmatrix.sync.aligned.m8n8.x4.shared.b16 {%0,%1,%2,%3}, [%4];"
                 : "=r"(r0), "=r"(r1), "=r"(r2), "=r"(r3) : "r"(addr));
}

// ---------------- tensor-core GEMM: C[M,N] = (Ah+Al)[M,K] @ (Bh+Bl)[N,K]^T ----------------
// 3-pass bf16 split (hh + hl + lh). fp32 accumulate. ldmatrix fragment loads.
// EPI: 0 fp32 out; 1 bias+relu -> bf16 hi/lo; 2 relu -> bf16 hi/lo; 4 fp32 accumulate (Cf += v)
// Requires M%128==0, N%128==0, K%16==0.
#define SPAD 16
template<int EPI>
__global__ __launch_bounds__(256) void gemm_bf3(
    const bf16* __restrict__ Ah, const bf16* __restrict__ Al,
    const bf16* __restrict__ Bh, const bf16* __restrict__ Bl,
    const float* __restrict__ bias,
    bf16* __restrict__ Ch, bf16* __restrict__ Cl, float* __restrict__ Cf,
    int M, int N, int K)
{
    __shared__ __align__(16) bf16 sAh[2][128][SPAD];
    __shared__ __align__(16) bf16 sAl[2][128][SPAD];
    __shared__ __align__(16) bf16 sBh[2][128][SPAD];
    __shared__ __align__(16) bf16 sBl[2][128][SPAD];

    const int tid = threadIdx.x;
    const int m0 = blockIdx.y * 128;
    const int n0 = blockIdx.x * 128;
    const int wid = tid >> 5, lane = tid & 31;
    const int wm = wid & 3;
    const int wn = wid >> 2;
    const int lr = lane >> 2, lc = lane & 3;

    // ldmatrix address geometry: group = lane/8 selects matrix, gi = lane%8 its row
    const int grp = lane >> 3, gi = lane & 7;
    // A x4: matrices (r,0),(r+8,0),(r,8),(r+8,8) -> regs a0..a3
    const int arow_off = (grp & 1) * 8 + gi;
    const int acol     = (grp >> 1) * 8;
    // B x4 (covers tn, tn+1): matrices (n,0),(n,8),(n+8,0),(n+8,8) -> regs b[tn][0],b[tn][1],b[tn+1][0],b[tn+1][1]
    const int brow_off = (grp >> 1) * 8 + gi;
    const int bcol     = (grp & 1) * 8;

    float acc[2][8][4];
#pragma unroll
    for (int tm = 0; tm < 2; tm++)
#pragma unroll
        for (int tn = 0; tn < 8; tn++)
#pragma unroll
            for (int q = 0; q < 4; q++) acc[tm][tn][q] = 0.f;

    const int lrow0 = tid >> 2;
    const int lq    = tid & 3;

    // prologue: stage 0
#pragma unroll
    for (int i = 0; i < 2; i++) {
        int row = lrow0 + i * 64;
        *(uint2*)(&sAh[0][row][lq * 4]) = *(const uint2*)(Ah + (size_t)(m0 + row) * K + lq * 4);
        *(uint2*)(&sAl[0][row][lq * 4]) = *(const uint2*)(Al + (size_t)(m0 + row) * K + lq * 4);
        *(uint2*)(&sBh[0][row][lq * 4]) = *(const uint2*)(Bh + (size_t)(n0 + row) * K + lq * 4);
        *(uint2*)(&sBl[0][row][lq * 4]) = *(const uint2*)(Bl + (size_t)(n0 + row) * K + lq * 4);
    }
    __syncthreads();

    int buf = 0;
    for (int k0 = 0; k0 < K; k0 += 16) {
        const bool more = (k0 + 16) < K;
        uint2 pf[4][2];
        if (more) {
#pragma unroll
            for (int i = 0; i < 2; i++) {
                int row = lrow0 + i * 64;
                size_t ka = (size_t)(m0 + row) * K + k0 + 16 + lq * 4;
                size_t kb = (size_t)(n0 + row) * K + k0 + 16 + lq * 4;
                pf[0][i] = *(const uint2*)(Ah + ka);
                pf[1][i] = *(const uint2*)(Al + ka);
                pf[2][i] = *(const uint2*)(Bh + kb);
                pf[3][i] = *(const uint2*)(Bl + kb);
            }
        }

        // fragment loads via ldmatrix
        unsigned ah[2][4], al[2][4], bh[8][2], bl[8][2];
#pragma unroll
        for (int tm = 0; tm < 2; tm++) {
            int r = wm * 32 + tm * 16 + arow_off;
            ldsm_x4(ah[tm][0], ah[tm][1], ah[tm][2], ah[tm][3], &sAh[buf][r][acol]);
            ldsm_x4(al[tm][0], al[tm][1], al[tm][2], al[tm][3], &sAl[buf][r][acol]);
        }
#pragma unroll
        for (int tp = 0; tp < 4; tp++) {
            int r = wn * 64 + tp * 16 + brow_off;
            ldsm_x4(bh[tp*2][0], bh[tp*2][1], bh[tp*2+1][0], bh[tp*2+1][1], &sBh[buf][r][bcol]);
            ldsm_x4(bl[tp*2][0], bl[tp*2][1], bl[tp*2+1][0], bl[tp*2+1][1], &sBl[buf][r][bcol]);
        }

        // 3 passes: hi*hi, hi*lo, lo*hi
#pragma unroll
        for (int tm = 0; tm < 2; tm++)
#pragma unroll
            for (int tn = 0; tn < 8; tn++)
                mma_bf16(acc[tm][tn], ah[tm], bh[tn]);
#pragma unroll
        for (int tm = 0; tm < 2; tm++)
#pragma unroll
            for (int tn = 0; tn < 8; tn++)
                mma_bf16(acc[tm][tn], ah[tm], bl[tn]);
#pragma unroll
        for (int tm = 0; tm < 2; tm++)
#pragma unroll
            for (int tn = 0; tn < 8; tn++)
                mma_bf16(acc[tm][tn], al[tm], bh[tn]);

        if (more) {
            int nb = buf ^ 1;
            // stores target the OTHER buffer -> safe before the barrier
#pragma unroll
            for (int i = 0; i < 2; i++) {
                int row = lrow0 + i * 64;
                *(uint2*)(&sAh[nb][row][lq * 4]) = pf[0][i];
                *(uint2*)(&sAl[nb][row][lq * 4]) = pf[1][i];
                *(uint2*)(&sBh[nb][row][lq * 4]) = pf[2][i];
                *(uint2*)(&sBl[nb][row][lq * 4]) = pf[3][i];
            }
            __syncthreads();   // single barrier per k-tile
            buf = nb;
        }
    }

    // epilogue
#pragma unroll
    for (int tm = 0; tm < 2; tm++) {
#pragma unroll
        for (int tn = 0; tn < 8; tn++) {
            int row = m0 + wm * 32 + tm * 16 + lr;
            int col = n0 + wn * 64 + tn * 8 + lc * 2;
            const float* a = acc[tm][tn];
#pragma unroll
            for (int q = 0; q < 4; q++) {
                int r = row + (q >> 1) * 8;
                int c = col + (q & 1);
                float v = a[q];
                size_t idx = (size_t)r * N + c;
                if (EPI == 0) {
                    Cf[idx] = v;
                } else if (EPI == 4) {
                    Cf[idx] += v;
                } else {
                    if (EPI == 1) v += bias[c];
                    v = fmaxf(v, 0.f);
                    bf16 h, l; bf16_split(v, h, l);
                    Ch[idx] = h; Cl[idx] = l;
                }
            }
        }
    }
}

// ---------------- weight split: fp32 -> bf16 hi/lo (vectorized, n % 4 == 0) ----------------
__global__ void split_w_kernel(const float* __restrict__ w,
                               bf16* __restrict__ wh, bf16* __restrict__ wl, int n)
{
    int i = (blockIdx.x * 256 + threadIdx.x) * 4;
    if (i < n) {
        float4 v = *(const float4*)(w + i);
        bf16 h0, l0, h1, l1, h2, l2, h3, l3;
        bf16_split(v.x, h0, l0); bf16_split(v.y, h1, l1);
        bf16_split(v.z, h2, l2); bf16_split(v.w, h3, l3);
        bf16 hv[4] = {h0, h1, h2, h3};
        bf16 lv[4] = {l0, l1, l2, l3};
        *(uint2*)(wh + i) = *(const uint2*)hv;
        *(uint2*)(wl + i) = *(const uint2*)lv;
    }
}

// ---------------- generic fp32 GEMM: C[M,N] = A[M,K] @ B[N,K]^T ----------------
// EPI: 0 none, 3 bias+softplus
template<int EPI>
__global__ __launch_bounds__(256) void gemm_tn(
    const float* __restrict__ A, const float* __restrict__ Bw,
    const float* __restrict__ bias, float* __restrict__ C,
    int M, int N, int K)
{
    __shared__ float As[2][16][128];
    __shared__ float Bs[2][16][128];
    const int tid = threadIdx.x;
    const int m0 = blockIdx.y * 128;
    const int n0 = blockIdx.x * 128;
    const int tx = tid & 15;
    const int ty = tid >> 4;

    float acc[8][8];
#pragma unroll
    for (int i = 0; i < 8; i++)
#pragma unroll
        for (int j = 0; j < 8; j++) acc[i][j] = 0.f;

    const int lrow = tid >> 1;
    const int lcol = (tid & 1) * 8;
    const float* Aptr = A + (size_t)(m0 + lrow) * K + lcol;
    const bool bvalid = (n0 + lrow) < N;
    const float* Bptr = Bw + (size_t)(n0 + lrow) * K + lcol;

    {
        float4 a0 = *(const float4*)(Aptr);
        float4 a1 = *(const float4*)(Aptr + 4);
        float4 b0 = make_float4(0.f, 0.f, 0.f, 0.f);
        float4 b1 = make_float4(0.f, 0.f, 0.f, 0.f);
        if (bvalid) {
            b0 = *(const float4*)(Bptr);
            b1 = *(const float4*)(Bptr + 4);
        }
        As[0][lcol + 0][lrow] = a0.x; As[0][lcol + 1][lrow] = a0.y;
        As[0][lcol + 2][lrow] = a0.z; As[0][lcol + 3][lrow] = a0.w;
        As[0][lcol + 4][lrow] = a1.x; As[0][lcol + 5][lrow] = a1.y;
        As[0][lcol + 6][lrow] = a1.z; As[0][lcol + 7][lrow] = a1.w;
        Bs[0][lcol + 0][lrow] = b0.x; Bs[0][lcol + 1][lrow] = b0.y;
        Bs[0][lcol + 2][lrow] = b0.z; Bs[0][lcol + 3][lrow] = b0.w;
        Bs[0][lcol + 4][lrow] = b1.x; Bs[0][lcol + 5][lrow] = b1.y;
        Bs[0][lcol + 6][lrow] = b1.z; Bs[0][lcol + 7][lrow] = b1.w;
    }
    __syncthreads();

    int nbuf = 1;
    for (int k0 = 0; k0 < K; k0 += 16) {
        const int cur = nbuf ^ 1;
        const bool more = (k0 + 16) < K;

        float4 a0, a1, b0, b1;
        if (more) {
            a0 = *(const float4*)(Aptr + k0 + 16);
            a1 = *(const float4*)(Aptr + k0 + 20);
            b0 = make_float4(0.f, 0.f, 0.f, 0.f);
            b1 = make_float4(0.f, 0.f, 0.f, 0.f);
            if (bvalid) {
                b0 = *(const float4*)(Bptr + k0 + 16);
                b1 = *(const float4*)(Bptr + k0 + 20);
            }
        }

#pragma unroll
        for (int kk = 0; kk < 16; kk++) {
            float ra[8], rb[8];
            *(float4*)(ra)     = *(const float4*)(&As[cur][kk][ty * 8]);
            *(float4*)(ra + 4) = *(const float4*)(&As[cur][kk][ty * 8 + 4]);
            *(float4*)(rb)     = *(const float4*)(&Bs[cur][kk][tx * 8]);
            *(float4*)(rb + 4) = *(const float4*)(&Bs[cur][kk][tx * 8 + 4]);
#pragma unroll
            for (int i = 0; i < 8; i++)
#pragma unroll
                for (int j = 0; j < 8; j++)
                    acc[i][j] = fmaf(ra[i], rb[j], acc[i][j]);
        }
        __syncthreads();

        if (more) {
            As[nbuf][lcol + 0][lrow] = a0.x; As[nbuf][lcol + 1][lrow] = a0.y;
            As[nbuf][lcol + 2][lrow] = a0.z; As[nbuf][lcol + 3][lrow] = a0.w;
            As[nbuf][lcol + 4][lrow] = a1.x; As[nbuf][lcol + 5][lrow] = a1.y;
            As[nbuf][lcol + 6][lrow] = a1.z; As[nbuf][lcol + 7][lrow] = a1.w;
            Bs[nbuf][lcol + 0][lrow] = b0.x; Bs[nbuf][lcol + 1][lrow] = b0.y;
            Bs[nbuf][lcol + 2][lrow] = b0.z; Bs[nbuf][lcol + 3][lrow] = b0.w;
            Bs[nbuf][lcol + 4][lrow] = b1.x; Bs[nbuf][lcol + 5][lrow] = b1.y;
            Bs[nbuf][lcol + 6][lrow] = b1.z; Bs[nbuf][lcol + 7][lrow] = b1.w;
            __syncthreads();
            nbuf ^= 1;
        }
    }

    const int mbase = m0 + ty * 8;
    const int nbase = n0 + tx * 8;
#pragma unroll
    for (int i = 0; i < 8; i++) {
#pragma unroll
        for (int j = 0; j < 8; j++) {
            int n = nbase + j;
            if (n >= N) continue;
            size_t idx = (size_t)(mbase + i) * N + n;
            float v = acc[i][j];
            if (EPI == 0) {
                C[idx] = v;
            } else { // 3
                float u = v + bias[n];
                C[idx] = (u > 15.f) ? u : log1pf(expf(u));
            }
        }
    }
}

// ---------------- RMSNorm over last dim DM -> bf16 hi/lo ----------------
__global__ void rmsnorm_kernel(const float* __restrict__ h,
                               const float* __restrict__ w,
                               bf16* __restrict__ oh, bf16* __restrict__ ol)
{
    __shared__ float red[256];
    int row = blockIdx.x;
    const float* hr = h + (size_t)row * DMD;
    float s = 0.f;
    for (int j = threadIdx.x; j < DMD; j += 256) { float v = hr[j]; s += v * v; }
    red[threadIdx.x] = s; __syncthreads();
    for (int o = 128; o > 0; o >>= 1) {
        if (threadIdx.x < o) red[threadIdx.x] += red[threadIdx.x + o];
        __syncthreads();
    }
    float scale = rsqrtf(red[0] * (1.f / DMD) + 1e-5f);
    for (int j = threadIdx.x; j < DMD; j += 256) {
        float v = hr[j] * scale * w[j];
        bf16 hh, ll; bf16_split(v, hh, ll);
        size_t id = (size_t)row * DMD + j;
        oh[id] = hh; ol[id] = ll;
    }
}

// ---------------- fused 2x depthwise conv (DCONV=2, causal) + SiLU ----------------
__global__ void conv_silu_kernel(const float* __restrict__ xz,
                                 const float* __restrict__ c1w, const float* __restrict__ c1b,
                                 const float* __restrict__ c2w, const float* __restrict__ c2b,
                                 float* __restrict__ xs)
{
    size_t idx = (size_t)blockIdx.x * blockDim.x + threadIdx.x;
    if (idx >= (size_t)MROWS * EDD) return;
    int e  = (int)(idx & (EDD - 1));
    int bl = (int)(idx >> 11);
    int l  = bl & (LL - 1);
    float x0  = xz[(size_t)bl * (2 * EDD) + e];
    float xm1 = (l >= 1) ? xz[(size_t)(bl - 1) * (2 * EDD) + e] : 0.f;
    float xm2 = (l >= 2) ? xz[(size_t)(bl - 2) * (2 * EDD) + e] : 0.f;
    float w10 = c1w[e * 2 + 0], w11 = c1w[e * 2 + 1], b1 = c1b[e];
    float w20 = c2w[e * 2 + 0], w21 = c2w[e * 2 + 1], b2 = c2b[e];
    float t1l   = b1 + w10 * xm1 + w11 * x0;
    float t1lm1 = (l >= 1) ? (b1 + w10 * xm2 + w11 * xm1) : 0.f;
    float u = b2 + w20 * t1lm1 + w21 * t1l;
    xs[idx] = u / (1.f + expf(-u));
}

// ---------------- split dC into dr (cols<64) and C (cols 64..65) ----------------
__global__ void split_dC_kernel(const float* __restrict__ dC,
                                float* __restrict__ dr, float* __restrict__ Cm)
{
    int idx = blockIdx.x * blockDim.x + threadIdx.x;
    if (idx >= MROWS * NCD) return;
    int m = idx / NCD, c = idx % NCD;
    float v = dC[idx];
    if (c < DTRD) dr[m * DTRD + c] = v;
    else          Cm[m * NSTD + (c - DTRD)] = v;
}

// ---------------- Kerr = softsign((xg - yh)^2) -> bf16 hi/lo ----------------
__global__ void kerr_kernel(const float* __restrict__ xs,
                            const float* __restrict__ y,
                            bf16* __restrict__ keh, bf16* __restrict__ kel, int s0)
{
    size_t idx = (size_t)blockIdx.x * blockDim.x + threadIdx.x;
    if (idx >= (size_t)MSEG * EDD) return;
    int e  = (int)(idx & (EDD - 1));
    int bt = (int)(idx >> 11);
    int t = bt & (SEGD - 1);
    int b = bt >> 8;
    size_t src = ((size_t)(b * LL + s0 + t)) * EDD + e;
    float xg = xs[src];
    float yh = (s0 > 0) ? y[((size_t)(b * LL + s0 - SEGD + t)) * EDD + e] : 0.f;
    float d = xg - yh;
    float u = d * d;
    float v = u / (1.f + u);
    bf16 h, l; bf16_split(v, h, l);
    keh[idx] = h; kel[idx] = l;
}

// ---------------- LayerNorm(Knew) + EMA update of K ----------------
__global__ void ln_kupdate_kernel(const float* __restrict__ Kn,
                                  const float* __restrict__ lng, const float* __restrict__ lnb,
                                  const float* __restrict__ ka, float* __restrict__ Kst)
{
    __shared__ float srow[EDD];
    __shared__ float red[256];
    int row = blockIdx.x;
    int tid = threadIdx.x;
    const float* hr = Kn + (size_t)row * EDD;
    float s = 0.f;
    for (int j = tid; j < EDD; j += 256) { float v = hr[j]; srow[j] = v; s += v; }
    red[tid] = s; __syncthreads();
    for (int o = 128; o > 0; o >>= 1) {
        if (tid < o) red[tid] += red[tid + o];
        __syncthreads();
    }
    float mu = red[0] * (1.f / EDD);
    __syncthreads();
    float s2 = 0.f;
    for (int j = tid; j < EDD; j += 256) { float d = srow[j] - mu; s2 += d * d; }
    red[tid] = s2; __syncthreads();
    for (int o = 128; o > 0; o >>= 1) {
        if (tid < o) red[tid] += red[tid + o];
        __syncthreads();
    }
    float rstd = rsqrtf(red[0] * (1.f / EDD) + 1e-5f);
    for (int j = tid; j < EDD; j += 256) {
        float o = lng[j] * (srow[j] - mu) * rstd + lnb[j];
        float a = fminf(fmaxf(ka[j], 0.01f), 0.99f);
        size_t id = (size_t)row * EDD + j;
        Kst[id] = (1.f - a) * Kst[id] + a * o;
    }
}

// ---------------- fused FDU (DFT filter) + segment scan, 2 channels/thread ----------------
// Thread t serves frequency t (filter) and time t (scan); processes channels e0, e0+1.
__global__ void fdu_scan_kernel(const float* __restrict__ xs,
                                const float* __restrict__ delta,
                                const float* __restrict__ Cm,
                                const float* __restrict__ Kst,
                                const float* __restrict__ Alog,
                                const float* __restrict__ Dp,
                                const float* __restrict__ sigma,
                                int layer, int s0,
                                float* __restrict__ y)
{
    __shared__ float2 sx2[SEGD];    // two channels of x
    __shared__ float2 stw[SEGD];    // (cos, sin) twiddles
    __shared__ float4 sS[SEGD];     // spectra: (re0, im0, re1, im1)
    __shared__ float2 sa0[SEGD], sb0[SEGD], sa1[SEGD], sb1[SEGD];

    int t = threadIdx.x;
    int be = blockIdx.x;                 // b * (ED/2) + e-pair
    int b  = be >> 10;
    int e0 = (be & 1023) * 2;
    size_t rowL = ((size_t)(b * LL + s0 + t)) * EDD + e0;
    size_t rowS = ((size_t)(b * SEGD + t)) * EDD + e0;

    float cc, ss;
    sincospif((float)t * (1.0f / 128.0f), &ss, &cc);   // angle 2*pi*t/256
    stw[t] = make_float2(cc, ss);
    float2 xg = *(const float2*)(xs + rowL);
    float2 dg = *(const float2*)(delta + rowL);
    float2 kv = *(const float2*)(Kst + rowS);
    sx2[t] = xg;
    __syncthreads();

    // forward DFT at frequency k = t (both channels)
    float xr0 = 0.f, xi0 = 0.f, xr1 = 0.f, xi1 = 0.f;
    for (int tt = 0; tt < SEGD; tt++) {
        int id = (t * tt) & (SEGD - 1);
        float2 w2 = stw[id];
        float2 v = sx2[tt];
        xr0 += v.x * w2.x; xi0 -= v.x * w2.y;
        xr1 += v.y * w2.x; xi1 -= v.y * w2.y;
    }
    float fk = (t < 128) ? (float)t * (1.0f / 256.0f) : (float)(t - 256) * (1.0f / 256.0f);
    float sg = sigma[layer];
    float base = 6.283185307179586f * fk * expf(-fk * fk * sg * sg);
    float w0 = base / (dg.x + 1e-5f);
    float w1 = base / (dg.y + 1e-5f);
    sS[t] = make_float4(-w0 * xi0, w0 * xr0, -w1 * xi1, w1 * xr1);
    __syncthreads();

    // inverse DFT (real part) at time t (both channels)
    float acc0 = 0.f, acc1 = 0.f;
    for (int kk = 0; kk < SEGD; kk++) {
        int id = (kk * t) & (SEGD - 1);
        float4 S = sS[kk];
        float2 w2 = stw[id];
        acc0 += S.x * w2.x - S.y * w2.y;
        acc1 += S.z * w2.x - S.w * w2.y;
    }
    float kdy0 = kv.x * acc0 * (1.0f / 256.0f);
    float kdy1 = kv.y * acc1 * (1.0f / 256.0f);

    // ----- scan (both channels) -----
    float C0 = Cm[(size_t)(b * LL + s0 + t) * NSTD + 0];
    float C1 = Cm[(size_t)(b * LL + s0 + t) * NSTD + 1];
    float4 Alr = *(const float4*)(Alog + (size_t)e0 * NSTD);   // A_log[e0][0..1], A_log[e0+1][0..1]
    float A00 = -expf(Alr.x), A01 = -expf(Alr.y);   // channel 0, states 0/1
    float A10 = -expf(Alr.z), A11 = -expf(Alr.w);   // channel 1

    // channel 0
    float KC0 = kv.x * C0, KC1 = kv.x * C1;
    float AmK0 = A00 * (1.f - KC0), AmK1 = A01 * (1.f - KC1);
    float Ak0 = AmK0 * (1.f + KC0), Ak1 = AmK1 * (1.f + KC1);
    float a0c0 = expf(dg.x * Ak0), a1c0 = expf(dg.x * Ak1);
    float b0c0 = dg.x * (-AmK0 * kv.x) * xg.x + kdy0;
    float b1c0 = dg.x * (-AmK1 * kv.x) * xg.x + kdy0;
    // channel 1
    float KD0 = kv.y * C0, KD1 = kv.y * C1;
    float BmK0 = A10 * (1.f - KD0), BmK1 = A11 * (1.f - KD1);
    float Bk0 = BmK0 * (1.f + KD0), Bk1 = BmK1 * (1.f + KD1);
    float a0c1 = expf(dg.y * Bk0), a1c1 = expf(dg.y * Bk1);
    float b0c1 = dg.y * (-BmK0 * kv.y) * xg.y + kdy1;
    float b1c1 = dg.y * (-BmK1 * kv.y) * xg.y + kdy1;

    sa0[t] = make_float2(a0c0, a0c1); sb0[t] = make_float2(b0c0, b0c1);
    sa1[t] = make_float2(a1c0, a1c1); sb1[t] = make_float2(b1c0, b1c1);
    __syncthreads();
    for (int d = 1; d < SEGD; d <<= 1) {
        float2 pa0, pb0, pa1, pb1;
        if (t >= d) { pa0 = sa0[t - d]; pb0 = sb0[t - d]; pa1 = sa1[t - d]; pb1 = sb1[t - d]; }
        __syncthreads();
        if (t >= d) {
            float2 ca0 = sa0[t], cb0 = sb0[t], ca1 = sa1[t], cb1 = sb1[t];
            sb0[t] = make_float2(ca0.x * pb0.x + cb0.x, ca0.y * pb0.y + cb0.y);
            sa0[t] = make_float2(ca0.x * pa0.x, ca0.y * pa0.y);
            sb1[t] = make_float2(ca1.x * pb1.x + cb1.x, ca1.y * pb1.y + cb1.y);
            sa1[t] = make_float2(ca1.x * pa1.x, ca1.y * pa1.y);
        }
        __syncthreads();
    }
    float2 h0 = sb0[t], h1 = sb1[t];
    float2 dp2 = *(const float2*)(Dp + e0);
    float2 out;
    out.x = h0.x * C0 + h1.x * C1 + dp2.x * xg.x;
    out.y = h0.y * C0 + h1.y * C1 + dp2.y * xg.y;
    *(float2*)(y + rowL) = out;
}

// ---------------- gate: g = y * silu(z) -> bf16 hi/lo ----------------
__global__ void gate_kernel(const float* __restrict__ y, const float* __restrict__ xz,
                            bf16* __restrict__ gh, bf16* __restrict__ gl)
{
    size_t idx = (size_t)blockIdx.x * blockDim.x + threadIdx.x;
    if (idx >= (size_t)MROWS * EDD) return;
    int e = (int)(idx & (EDD - 1));
    int m = (int)(idx >> 11);
    float z = xz[(size_t)m * (2 * EDD) + EDD + e];
    float v = y[idx] * (z / (1.f + expf(-z)));
    bf16 h, l; bf16_split(v, h, l);
    gh[idx] = h; gl[idx] = l;
}

// ---------------- host driver ----------------
extern "C" void kernel_launch(void* const* d_in, const int* in_sizes, int n_in,
                              void* d_out, int out_size)
{
    const float* x      = (const float*)d_in[0];
    const float* rms_w  = (const float*)d_in[1];
    const float* in_w   = (const float*)d_in[2];
    const float* c1_w   = (const float*)d_in[3];
    const float* c1_b   = (const float*)d_in[4];
    const float* c2_w   = (const float*)d_in[5];
    const float* c2_b   = (const float*)d_in[6];
    const float* xp_w   = (const float*)d_in[7];
    const float* dt_w   = (const float*)d_in[8];
    const float* dt_b   = (const float*)d_in[9];
    const float* A_log  = (const float*)d_in[10];
    const float* Dp     = (const float*)d_in[11];
    const float* out_w  = (const float*)d_in[12];
    const float* k1_w   = (const float*)d_in[13];
    const float* k1_b   = (const float*)d_in[14];
    const float* k2_w   = (const float*)d_in[15];
    const float* k3_w   = (const float*)d_in[16];
    const float* ln_g   = (const float*)d_in[17];
    const float* ln_b   = (const float*)d_in[18];
    const float* k_alpha= (const float*)d_in[19];
    const float* sigma  = (const float*)d_in[20];
    float* h = (float*)d_out;

    float *xz, *xs, *dC, *dr, *Cm, *delta, *y, *K, *Knew;
    bf16 *xnh, *xnl, *gh, *gl, *keh, *kel, *h1h, *h1l, *h2h, *h2l;
    bf16 *wih, *wil, *woh, *wol, *w1h, *w1l, *w2h, *w2l, *w3h, *w3l;
    cudaGetSymbolAddress((void**)&xz,    g_xz);
    cudaGetSymbolAddress((void**)&xs,    g_xs);
    cudaGetSymbolAddress((void**)&dC,    g_dC);
    cudaGetSymbolAddress((void**)&dr,    g_dr);
    cudaGetSymbolAddress((void**)&Cm,    g_Cm);
    cudaGetSymbolAddress((void**)&delta, g_delta);
    cudaGetSymbolAddress((void**)&y,     g_y);
    cudaGetSymbolAddress((void**)&K,     g_K);
    cudaGetSymbolAddress((void**)&Knew,  g_Knew);
    cudaGetSymbolAddress((void**)&xnh,   g_xnh);
    cudaGetSymbolAddress((void**)&xnl,   g_xnl);
    cudaGetSymbolAddress((void**)&gh,    g_gh);
    cudaGetSymbolAddress((void**)&gl,    g_gl);
    cudaGetSymbolAddress((void**)&keh,   g_keh);
    cudaGetSymbolAddress((void**)&kel,   g_kel);
    cudaGetSymbolAddress((void**)&h1h,   g_h1h);
    cudaGetSymbolAddress((void**)&h1l,   g_h1l);
    cudaGetSymbolAddress((void**)&h2h,   g_h2h);
    cudaGetSymbolAddress((void**)&h2l,   g_h2l);
    cudaGetSymbolAddress((void**)&wih,   g_wih);
    cudaGetSymbolAddress((void**)&wil,   g_wil);
    cudaGetSymbolAddress((void**)&woh,   g_woh);
    cudaGetSymbolAddress((void**)&wol,   g_wol);
    cudaGetSymbolAddress((void**)&w1h,   g_w1h);
    cudaGetSymbolAddress((void**)&w1l,   g_w1l);
    cudaGetSymbolAddress((void**)&w2h,   g_w2h);
    cudaGetSymbolAddress((void**)&w2l,   g_w2l);
    cudaGetSymbolAddress((void**)&w3h,   g_w3h);
    cudaGetSymbolAddress((void**)&w3l,   g_w3l);

    cudaMemcpyAsync(h, x, (size_t)MROWS * DMD * sizeof(float), cudaMemcpyDeviceToDevice);

    for (int i = 0; i < 2; i++) {
        const float* in_wi  = in_w  + (size_t)i * 2 * EDD * DMD;
        const float* c1_wi  = c1_w  + (size_t)i * EDD * 2;
        const float* c1_bi  = c1_b  + (size_t)i * EDD;
        const float* c2_wi  = c2_w  + (size_t)i * EDD * 2;
        const float* c2_bi  = c2_b  + (size_t)i * EDD;
        const float* xp_wi  = xp_w  + (size_t)i * NCD * EDD;
        const float* dt_wi  = dt_w  + (size_t)i * EDD * DTRD;
        const float* dt_bi  = dt_b  + (size_t)i * EDD;
        const float* Alogi  = A_log + (size_t)i * EDD * NSTD;
        const float* Dpi    = Dp    + (size_t)i * EDD;
        const float* out_wi = out_w + (size_t)i * DMD * EDD;
        const float* k1_wi  = k1_w  + (size_t)i * 3 * EDD * EDD;
        const float* k1_bi  = k1_b  + (size_t)i * 3 * EDD;
        const float* k2_wi  = k2_w  + (size_t)i * EDD * 3 * EDD;
        const float* k3_wi  = k3_w  + (size_t)i * EDD * EDD;
        const float* ln_gi  = ln_g  + (size_t)i * EDD;
        const float* ln_bi  = ln_b  + (size_t)i * EDD;
        const float* kai    = k_alpha + (size_t)i * EDD;
        const float* rmsi   = rms_w + (size_t)i * DMD;

        // weight splits for this layer's tensor-core GEMMs (vectorized x4)
        split_w_kernel<<<(2 * EDD * DMD / 4 + 255) / 256, 256>>>(in_wi, wih, wil, 2 * EDD * DMD);
        split_w_kernel<<<(DMD * EDD / 4 + 255) / 256, 256>>>(out_wi, woh, wol, DMD * EDD);
        split_w_kernel<<<(3 * EDD * EDD / 4 + 255) / 256, 256>>>(k1_wi, w1h, w1l, 3 * EDD * EDD);
        split_w_kernel<<<(3 * EDD * EDD / 4 + 255) / 256, 256>>>(k2_wi, w2h, w2l, 3 * EDD * EDD);
        split_w_kernel<<<(EDD * EDD / 4 + 255) / 256, 256>>>(k3_wi, w3h, w3l, EDD * EDD);

        rmsnorm_kernel<<<MROWS, 256>>>(h, rmsi, xnh, xnl);

        // in-proj: xz = xn @ in_w^T  (tensor cores)
        gemm_bf3<0><<<dim3(2 * EDD / 128, MROWS / 128), 256>>>(
            xnh, xnl, wih, wil, nullptr, nullptr, nullptr, xz, MROWS, 2 * EDD, DMD);

        conv_silu_kernel<<<(MROWS * EDD) / 256, 256>>>(xz, c1_wi, c1_bi, c2_wi, c2_bi, xs);

        gemm_tn<0><<<dim3(1, MROWS / 128), 256>>>(xs, xp_wi, nullptr, dC, MROWS, NCD, EDD);
        split_dC_kernel<<<(MROWS * NCD + 255) / 256, 256>>>(dC, dr, Cm);

        gemm_tn<3><<<dim3(EDD / 128, MROWS / 128), 256>>>(
            dr, dt_wi, dt_bi, delta, MROWS, EDD, DTRD);

        cudaMemsetAsync(K, 0, (size_t)MSEG * EDD * sizeof(float));

        for (int s = 0; s < NSEG; s++) {
            int s0 = s * SEGD;
            kerr_kernel<<<(MSEG * EDD) / 256, 256>>>(xs, y, keh, kel, s0);
            gemm_bf3<1><<<dim3(3 * EDD / 128, MSEG / 128), 256>>>(
                keh, kel, w1h, w1l, k1_bi, h1h, h1l, nullptr, MSEG, 3 * EDD, EDD);
            gemm_bf3<2><<<dim3(EDD / 128, MSEG / 128), 256>>>(
                h1h, h1l, w2h, w2l, nullptr, h2h, h2l, nullptr, MSEG, EDD, 3 * EDD);
            gemm_bf3<0><<<dim3(EDD / 128, MSEG / 128), 256>>>(
                h2h, h2l, w3h, w3l, nullptr, nullptr, nullptr, Knew, MSEG, EDD, EDD);
            ln_kupdate_kernel<<<MSEG, 256>>>(Knew, ln_gi, ln_bi, kai, K);
            fdu_scan_kernel<<<BB * EDD / 2, SEGD>>>(xs, delta, Cm, K, Alogi, Dpi, sigma, i, s0, y);
        }

        gate_kernel<<<(MROWS * EDD) / 256, 256>>>(y, xz, gh, gl);
        // out-proj: h += gate @ out_w^T  (tensor cores, accumulate)
        gemm_bf3<4><<<dim3(DMD / 128, MROWS / 128), 256>>>(
            gh, gl, woh, wol, nullptr, nullptr, nullptr, h, MROWS, DMD, EDD);
    }
}